// round 13
// baseline (speedup 1.0000x reference)
#include <cuda_runtime.h>
#include <cuda_bf16.h>
#include <math.h>
#include <stdint.h>

#define B_ROWS 65536
#define IN_DIM 256
#define G_DIM  512
#define W_DIM  512
#define LN_EPS 1e-5f

// ---------------- global scratch (device globals; no allocs) ----------------
__device__ uint8_t g_x8[(size_t)B_ROWS * IN_DIM];          // inputs s8 (x*16)
__device__ uint8_t g_c8[(size_t)G_DIM * IN_DIM];           // centers s8 (c*16)
__device__ __nv_bfloat16 g_wb[(size_t)W_DIM * G_DIM];      // W_mix bf16
__device__ __nv_bfloat16 g_scaled[(size_t)B_ROWS * G_DIM]; // RBF activations bf16
__device__ float g_xsq[B_ROWS];
__device__ float g_csq[G_DIM];
__device__ float g_s[G_DIM];
// nonzero flags: [m-tile of 64 rows][K-chunk of 64 cols] for g_scaled
__device__ int g_nz[(B_ROWS / 64) * 8];

// ---------------- PTX helpers (sm_80+ subset; compute_103-safe) -------------
__device__ __forceinline__ uint32_t smem_cast(const void* p) {
    return (uint32_t)__cvta_generic_to_shared(p);
}
__device__ __forceinline__ void cp16(uint32_t dst, const void* src) {
    asm volatile("cp.async.cg.shared.global [%0], [%1], 16;" :: "r"(dst), "l"(src));
}
#define CP_COMMIT() asm volatile("cp.async.commit_group;" ::: "memory")
#define CP_WAIT(n)  asm volatile("cp.async.wait_group %0;" :: "n"(n) : "memory")

__device__ __forceinline__ void ldsm4(uint32_t* r, uint32_t addr) {
    asm volatile("ldmatrix.sync.aligned.m8n8.x4.shared.b16 {%0,%1,%2,%3}, [%4];"
                 : "=r"(r[0]), "=r"(r[1]), "=r"(r[2]), "=r"(r[3]) : "r"(addr));
}
__device__ __forceinline__ void mma_bf16(float* d, const uint32_t* a,
                                         uint32_t b0, uint32_t b1) {
    asm volatile(
        "mma.sync.aligned.m16n8k16.row.col.f32.bf16.bf16.f32 "
        "{%0,%1,%2,%3}, {%4,%5,%6,%7}, {%8,%9}, {%0,%1,%2,%3};"
        : "+f"(d[0]), "+f"(d[1]), "+f"(d[2]), "+f"(d[3])
        : "r"(a[0]), "r"(a[1]), "r"(a[2]), "r"(a[3]), "r"(b0), "r"(b1));
}
__device__ __forceinline__ void mma_s8(int* d, const uint32_t* a,
                                       uint32_t b0, uint32_t b1) {
    asm volatile(
        "mma.sync.aligned.m16n8k32.row.col.s32.s8.s8.s32 "
        "{%0,%1,%2,%3}, {%4,%5,%6,%7}, {%8,%9}, {%0,%1,%2,%3};"
        : "+r"(d[0]), "+r"(d[1]), "+r"(d[2]), "+r"(d[3])
        : "r"(a[0]), "r"(a[1]), "r"(a[2]), "r"(a[3]), "r"(b0), "r"(b1));
}

// quantize 4 floats (scale 16, clamp +-127) -> packed s8x4
__device__ __forceinline__ uint32_t quant4_s8(float4 a) {
    int v0 = __float2int_rn(fminf(fmaxf(a.x * 16.f, -127.f), 127.f));
    int v1 = __float2int_rn(fminf(fmaxf(a.y * 16.f, -127.f), 127.f));
    int v2 = __float2int_rn(fminf(fmaxf(a.z * 16.f, -127.f), 127.f));
    int v3 = __float2int_rn(fminf(fmaxf(a.w * 16.f, -127.f), 127.f));
    return (uint32_t)(v0 & 0xFF) | ((uint32_t)(v1 & 0xFF) << 8) |
           ((uint32_t)(v2 & 0xFF) << 16) | ((uint32_t)(v3 & 0xFF) << 24);
}

// ---------------- merged prep kernel -----------------------------------------
// blocks [0, 8192)      : inputs -> s8 + xsq (+ g_nz reset in first 32 blocks)
// blocks [8192, 8256)   : centers -> s8 + csq + s
// blocks [8256, 8320)   : W -> bf16
__global__ __launch_bounds__(256) void conv_all(const float* __restrict__ x,
                                                const float* __restrict__ c,
                                                const float* __restrict__ ls,
                                                const float* __restrict__ w) {
    const int lane = threadIdx.x & 31;
    if (blockIdx.x < 8192) {
        const int gtid = blockIdx.x * 256 + threadIdx.x;
        if (gtid < (B_ROWS / 64) * 8) g_nz[gtid] = 0;
        int row = blockIdx.x * 8 + (threadIdx.x >> 5);
        const float* r = x + (size_t)row * IN_DIM;
        int k0 = lane * 8;
        float4 a0 = *(const float4*)(r + k0);
        float4 a1 = *(const float4*)(r + k0 + 4);
        float ss = a0.x*a0.x + a0.y*a0.y + a0.z*a0.z + a0.w*a0.w +
                   a1.x*a1.x + a1.y*a1.y + a1.z*a1.z + a1.w*a1.w;
#pragma unroll
        for (int o = 16; o > 0; o >>= 1) ss += __shfl_xor_sync(0xffffffffu, ss, o);
        if (lane == 0) g_xsq[row] = ss;
        *(uint2*)(g_x8 + (size_t)row * IN_DIM + k0) =
            make_uint2(quant4_s8(a0), quant4_s8(a1));
    } else if (blockIdx.x < 8256) {
        int g = (blockIdx.x - 8192) * 8 + (threadIdx.x >> 5);
        const float* r = c + (size_t)g * IN_DIM;
        int k0 = lane * 8;
        float4 a0 = *(const float4*)(r + k0);
        float4 a1 = *(const float4*)(r + k0 + 4);
        float ss = a0.x*a0.x + a0.y*a0.y + a0.z*a0.z + a0.w*a0.w +
                   a1.x*a1.x + a1.y*a1.y + a1.z*a1.z + a1.w*a1.w;
#pragma unroll
        for (int o = 16; o > 0; o >>= 1) ss += __shfl_xor_sync(0xffffffffu, ss, o);
        if (lane == 0) { g_csq[g] = ss; g_s[g] = expf(ls[g]); }
        *(uint2*)(g_c8 + (size_t)g * IN_DIM + k0) =
            make_uint2(quant4_s8(a0), quant4_s8(a1));
    } else {
        int wr = (blockIdx.x - 8256) * 8 + (threadIdx.x >> 5);
        const float* r = w + (size_t)wr * G_DIM;
#pragma unroll
        for (int part = 0; part < 2; part++) {
            int k0 = lane * 16 + part * 8;
            float4 a0 = *(const float4*)(r + k0);
            float4 a1 = *(const float4*)(r + k0 + 4);
            __nv_bfloat162 h0 = __floats2bfloat162_rn(a0.x, a0.y);
            __nv_bfloat162 h1 = __floats2bfloat162_rn(a0.z, a0.w);
            __nv_bfloat162 h2 = __floats2bfloat162_rn(a1.x, a1.y);
            __nv_bfloat162 h3 = __floats2bfloat162_rn(a1.z, a1.w);
            *(uint4*)(g_wb + (size_t)wr * G_DIM + k0) =
                make_uint4(*(uint32_t*)&h0, *(uint32_t*)&h1, *(uint32_t*)&h2, *(uint32_t*)&h3);
        }
    }
}

// ---------------- GEMM1 (RBF, s8): 128x128 tile, K=256 resident --------------
// cross = (x16 . c16) / 256 exact-int32; dist2 = xsq + csq - 2*cross (fp32)
#define P1 272
#define G1_B   (128 * P1)
#define G1_SMEM (2 * 128 * P1 + 1024)

__global__ __launch_bounds__(256, 2) void gemm1_rbf() {
    extern __shared__ __align__(16) uint8_t sm[];
    float* s_c0 = (float*)(sm + 2 * 128 * P1);
    float* s_c1 = s_c0 + 128;

    const int tid = threadIdx.x, lane = tid & 31, wid = tid >> 5;
    const int bm = blockIdx.y * 128, bn = blockIdx.x * 128;

    if (tid < 128) { s_c0[tid] = g_csq[bn + tid]; s_c1[tid] = g_s[bn + tid]; }

    const uint32_t sbase = smem_cast(sm);
#pragma unroll
    for (int i = 0; i < 8; i++) {
        const int v = i * 256 + tid;
        const int row = v >> 4, cb = (v & 15) * 16;
        cp16(sbase + (uint32_t)(row * P1 + cb), g_x8 + (size_t)(bm + row) * IN_DIM + cb);
    }
#pragma unroll
    for (int i = 0; i < 8; i++) {
        const int v = i * 256 + tid;
        const int row = v >> 4, cb = (v & 15) * 16;
        cp16(sbase + (uint32_t)(G1_B + row * P1 + cb), g_c8 + (size_t)(bn + row) * IN_DIM + cb);
    }
    CP_COMMIT();
    CP_WAIT(0);
    __syncthreads();

    const int m0 = (wid >> 2) * 64, n0 = (wid & 3) * 32;
    const int arow = lane & 15, acolb = (lane >> 4) * 16;
    const int brow = (lane & 7) | ((lane & 16) >> 1), bcolb = (lane & 8) * 2;

    int acc[4][4][4] = {};
    uint32_t af[2][4][4], bfr[2][2][4];

    auto load_frags = [&](int kk, int b) {
#pragma unroll
        for (int mf = 0; mf < 4; mf++)
            ldsm4(af[b][mf], sbase + (uint32_t)((m0 + mf * 16 + arow) * P1 + kk * 32 + acolb));
#pragma unroll
        for (int nh = 0; nh < 2; nh++)
            ldsm4(bfr[b][nh], sbase + (uint32_t)(G1_B + (n0 + nh * 16 + brow) * P1 + kk * 32 + bcolb));
    };
    auto do_mma = [&](int b) {
#pragma unroll
        for (int mf = 0; mf < 4; mf++)
#pragma unroll
            for (int nf = 0; nf < 4; nf++)
                mma_s8(acc[mf][nf], af[b][mf],
                       bfr[b][nf >> 1][(nf & 1) * 2], bfr[b][nf >> 1][(nf & 1) * 2 + 1]);
    };

    load_frags(0, 0);
#pragma unroll
    for (int kk = 0; kk < 8; kk++) {
        if (kk < 7) load_frags(kk + 1, (kk + 1) & 1);
        do_mma(kk & 1);
    }

    // epilogue: 2*cross = acc * (2/256) = acc * 0.0078125
    const int erow = lane >> 2, ecol = (lane & 3) * 2;
    const float DQ = 0.0078125f;  // 2/256
    uint32_t nzu = 0;
#pragma unroll
    for (int mf = 0; mf < 4; mf++) {
        const int gm0 = bm + m0 + mf * 16 + erow;
        const float xq0 = g_xsq[gm0], xq1 = g_xsq[gm0 + 8];
#pragma unroll
        for (int nf = 0; nf < 4; nf++) {
            const int cl = n0 + nf * 8 + ecol;
            const int gc = bn + cl;
            const float cq0 = s_c0[cl], ss0 = s_c1[cl];
            const float cq1 = s_c0[cl + 1], ss1 = s_c1[cl + 1];
            float v00 = __expf(((float)acc[mf][nf][0] * DQ - xq0 - cq0) * ss0);
            float v01 = __expf(((float)acc[mf][nf][1] * DQ - xq0 - cq1) * ss1);
            float v10 = __expf(((float)acc[mf][nf][2] * DQ - xq1 - cq0) * ss0);
            float v11 = __expf(((float)acc[mf][nf][3] * DQ - xq1 - cq1) * ss1);
            __nv_bfloat162 h0 = __floats2bfloat162_rn(v00, v01);
            __nv_bfloat162 h1 = __floats2bfloat162_rn(v10, v11);
            const uint32_t p0 = *(uint32_t*)&h0, p1 = *(uint32_t*)&h1;
            nzu |= p0 | p1;
            if (p0) *(uint32_t*)(g_scaled + (size_t)gm0 * G_DIM + gc) = p0;
            if (p1) *(uint32_t*)(g_scaled + (size_t)(gm0 + 8) * G_DIM + gc) = p1;
        }
    }
    const uint32_t any = __reduce_or_sync(0xffffffffu, nzu);
    if (lane == 0 && any)
        atomicOr(&g_nz[((bm + m0) >> 6) * 8 + ((bn + n0) >> 6)], 1);
}

// ---------------- GEMM2 + LayerNorm + tanh: persistent, 148 CTAs, 512 thr ----
#define G2P 72
#define G2_STG (576 * G2P)
#define G2_FLT ((size_t)G2_STG * 2)
#define G2_SMEM (G2_FLT + (512 * 6 + 128 + 32) * 4 + 64)
#define NTILES2 (B_ROWS / 64)

__global__ __launch_bounds__(512, 1) void gemm2_ln(const float* __restrict__ bias,
                                                   const float* __restrict__ gamma,
                                                   const float* __restrict__ beta,
                                                   float* __restrict__ out) {
    extern __shared__ __align__(16) __nv_bfloat16 smh[];
    float* vs_b  = (float*)((char*)smh + G2_FLT);
    float* vs_g  = vs_b + 512;
    float* vs_be = vs_g + 512;
    float* ybuf  = vs_be + 512;
    float* part_sum = ybuf + 512;
    float* part_sq  = part_sum + 512;
    float* stats    = part_sq + 512;
    float* red      = stats + 128;
    int*   s_nz     = (int*)(red + 32);

    const int tid = threadIdx.x, lane = tid & 31, wid = tid >> 5;

    vs_b[tid] = bias[tid]; vs_g[tid] = gamma[tid]; vs_be[tid] = beta[tid];
    __syncthreads();

    // once per CTA: ybuf = tanh(LN(bias))
    {
        const float v = vs_b[tid];
        float s = v, q = v * v;
#pragma unroll
        for (int o = 16; o > 0; o >>= 1) {
            s += __shfl_xor_sync(0xffffffffu, s, o);
            q += __shfl_xor_sync(0xffffffffu, q, o);
        }
        if (lane == 0) { red[wid] = s; red[wid + 16] = q; }
        __syncthreads();
        if (tid == 0) {
            float ts = 0.f, tq = 0.f;
#pragma unroll
            for (int w = 0; w < 16; w++) { ts += red[w]; tq += red[w + 16]; }
            const float mean = ts * (1.0f / 512.0f);
            const float var  = tq * (1.0f / 512.0f) - mean * mean;
            red[0] = mean;
            red[1] = rsqrtf(var + LN_EPS);
        }
        __syncthreads();
        ybuf[tid] = tanhf((v - red[0]) * red[1] * vs_g[tid] + vs_be[tid]);
    }
    __syncthreads();

    const uint32_t sb0 = smem_cast(smh);
    const int crow = tid >> 3, cc8 = (tid & 7) * 8;
    const int wr = wid >> 3, wc = wid & 7;
    const int arow = lane & 15, acol = (lane >> 4) << 3;
    const int brow = (lane & 7) | ((lane & 16) >> 1), bcol = lane & 8;
    const int ecol = (lane & 3) * 2;

    for (int tile = blockIdx.x; tile < NTILES2; tile += gridDim.x) {
        const int bm = tile * 64;
        if (tid < 8) s_nz[tid] = g_nz[tile * 8 + tid];
        __syncthreads();
        int act[8], nact = 0;
#pragma unroll
        for (int k = 0; k < 8; k++) if (s_nz[k]) act[nact++] = k;
        __syncthreads();

        // ---------- FAST PATH: broadcast ybuf to 64 rows ----------
        if (nact == 0) {
            const float4* y4 = (const float4*)ybuf;
            float4* o4 = (float4*)(out + (size_t)bm * W_DIM);
#pragma unroll
            for (int i = 0; i < 16; i++) {
                const int idx = tid + i * 512;
                __stcs(o4 + idx, y4[idx & 127]);
            }
            continue;
        }

        // ---------- SLOW PATH: single-stage block-sparse GEMM + LN ----------
        float acc[2][8][4] = {};
#pragma unroll 1
        for (int i = 0; i < nact; i++) {
            const int kc = act[i];
            cp16(sb0 + (uint32_t)(crow * G2P + cc8) * 2,
                 g_scaled + (size_t)(bm + crow) * G_DIM + kc * 64 + cc8);
#pragma unroll
            for (int j = 0; j < 8; j++) {
                const int r = crow + j * 64;
                cp16(sb0 + (uint32_t)((64 + r) * G2P + cc8) * 2,
                     g_wb + (size_t)r * G_DIM + kc * 64 + cc8);
            }
            CP_COMMIT();
            CP_WAIT(0);
            __syncthreads();
#pragma unroll
            for (int kk = 0; kk < 4; kk++) {
                uint32_t af[2][4], bfr[4][4];
#pragma unroll
                for (int mf = 0; mf < 2; mf++)
                    ldsm4(af[mf], sb0 + (uint32_t)((wr * 32 + mf * 16 + arow) * G2P +
                                                   kk * 16 + acol) * 2);
#pragma unroll
                for (int nh = 0; nh < 4; nh++)
                    ldsm4(bfr[nh], sb0 + (uint32_t)((64 + wc * 64 + nh * 16 + brow) * G2P +
                                                    kk * 16 + bcol) * 2);
#pragma unroll
                for (int mf = 0; mf < 2; mf++)
#pragma unroll
                    for (int nf = 0; nf < 8; nf++)
                        mma_bf16(acc[mf][nf], af[mf],
                                 bfr[nf >> 1][(nf & 1) * 2], bfr[nf >> 1][(nf & 1) * 2 + 1]);
            }
            __syncthreads();
        }

        // LayerNorm + tanh epilogue (fp32)
#pragma unroll
        for (int mf = 0; mf < 2; mf++) {
            float s0 = 0.f, q0 = 0.f, s1 = 0.f, q1 = 0.f;
#pragma unroll
            for (int nf = 0; nf < 8; nf++) {
                const int c = wc * 64 + nf * 8 + ecol;
                float v00 = acc[mf][nf][0] + vs_b[c];
                float v01 = acc[mf][nf][1] + vs_b[c + 1];
                float v10 = acc[mf][nf][2] + vs_b[c];
                float v11 = acc[mf][nf][3] + vs_b[c + 1];
                acc[mf][nf][0] = v00; acc[mf][nf][1] = v01;
                acc[mf][nf][2] = v10; acc[mf][nf][3] = v11;
                s0 += v00 + v01; q0 += v00 * v00 + v01 * v01;
                s1 += v10 + v11; q1 += v10 * v10 + v11 * v11;
            }
#pragma unroll
            for (int o = 1; o <= 2; o <<= 1) {
                s0 += __shfl_xor_sync(0xffffffffu, s0, o);
                q0 += __shfl_xor_sync(0xffffffffu, q0, o);
                s1 += __shfl_xor_sync(0xffffffffu, s1, o);
                q1 += __shfl_xor_sync(0xffffffffu, q1, o);
            }
            if ((lane & 3) == 0) {
                const int r0 = wr * 32 + mf * 16 + (lane >> 2);
                part_sum[r0 * 8 + wc] = s0;       part_sq[r0 * 8 + wc] = q0;
                part_sum[(r0 + 8) * 8 + wc] = s1; part_sq[(r0 + 8) * 8 + wc] = q1;
            }
        }
        __syncthreads();
        if (tid < 64) {
            float s = 0.f, q = 0.f;
#pragma unroll
            for (int w = 0; w < 8; w++) { s += part_sum[tid * 8 + w]; q += part_sq[tid * 8 + w]; }
            const float mean = s * (1.0f / 512.0f);
            const float var  = q * (1.0f / 512.0f) - mean * mean;
            stats[tid * 2] = mean;
            stats[tid * 2 + 1] = rsqrtf(var + LN_EPS);
        }
        __syncthreads();

#pragma unroll
        for (int mf = 0; mf < 2; mf++) {
            const int r0 = wr * 32 + mf * 16 + (lane >> 2), r1 = r0 + 8;
            const float m0 = stats[r0 * 2], rs0 = stats[r0 * 2 + 1];
            const float m1 = stats[r1 * 2], rs1 = stats[r1 * 2 + 1];
#pragma unroll
            for (int nf = 0; nf < 8; nf++) {
                const int c = wc * 64 + nf * 8 + ecol;
                const float g0 = vs_g[c], g1 = vs_g[c + 1];
                const float be0 = vs_be[c], be1 = vs_be[c + 1];
                float2 y0 = make_float2(tanhf((acc[mf][nf][0] - m0) * rs0 * g0 + be0),
                                        tanhf((acc[mf][nf][1] - m0) * rs0 * g1 + be1));
                float2 y1 = make_float2(tanhf((acc[mf][nf][2] - m1) * rs1 * g0 + be0),
                                        tanhf((acc[mf][nf][3] - m1) * rs1 * g1 + be1));
                *(float2*)(out + (size_t)(bm + r0) * W_DIM + c) = y0;
                *(float2*)(out + (size_t)(bm + r1) * W_DIM + c) = y1;
            }
        }
        __syncthreads();
    }
}

// ---------------------------------------------------------------------------
extern "C" void kernel_launch(void* const* d_in, const int* in_sizes, int n_in,
                              void* d_out, int out_size) {
    const float* inputs     = (const float*)d_in[0];
    const float* centers    = (const float*)d_in[1];
    const float* log_scales = (const float*)d_in[2];
    const float* W_mix      = (const float*)d_in[3];
    const float* b_mix      = (const float*)d_in[4];
    const float* ln_gamma   = (const float*)d_in[5];
    const float* ln_beta    = (const float*)d_in[6];
    float* out = (float*)d_out;

    cudaFuncSetAttribute(gemm1_rbf, cudaFuncAttributeMaxDynamicSharedMemorySize, G1_SMEM);
    cudaFuncSetAttribute(gemm2_ln,  cudaFuncAttributeMaxDynamicSharedMemorySize, (int)G2_SMEM);

    conv_all<<<8320, 256>>>(inputs, centers, log_scales, W_mix);
    gemm1_rbf<<<dim3(G_DIM / 128, B_ROWS / 128), 256, G1_SMEM>>>();
    gemm2_ln<<<148, 512, G2_SMEM>>>(b_mix, ln_gamma, ln_beta, out);
}

// round 14
// speedup vs baseline: 1.8564x; 1.8564x over previous
#include <cuda_runtime.h>
#include <cuda_bf16.h>
#include <cuda_fp8.h>
#include <math.h>
#include <stdint.h>

#define B_ROWS 65536
#define IN_DIM 256
#define G_DIM  512
#define W_DIM  512
#define LN_EPS 1e-5f

// ---------------- global scratch (device globals; no allocs) ----------------
__device__ uint8_t g_x8[(size_t)B_ROWS * IN_DIM];          // inputs e4m3
__device__ uint8_t g_c8[(size_t)G_DIM * IN_DIM];           // centers e4m3
__device__ __nv_bfloat16 g_wb[(size_t)W_DIM * G_DIM];      // W_mix bf16
__device__ __nv_bfloat16 g_scaled[(size_t)B_ROWS * G_DIM]; // RBF activations bf16
__device__ float g_xsq[B_ROWS];
__device__ float g_csq[G_DIM];
__device__ float g_s[G_DIM];

// ---------------- PTX helpers (sm_80/89+ subset; compute_103-safe) ----------
__device__ __forceinline__ uint32_t smem_cast(const void* p) {
    return (uint32_t)__cvta_generic_to_shared(p);
}
__device__ __forceinline__ void cp16(uint32_t dst, const void* src) {
    asm volatile("cp.async.cg.shared.global [%0], [%1], 16;" :: "r"(dst), "l"(src));
}
#define CP_COMMIT() asm volatile("cp.async.commit_group;" ::: "memory")
#define CP_WAIT(n)  asm volatile("cp.async.wait_group %0;" :: "n"(n) : "memory")

__device__ __forceinline__ void ldsm4(uint32_t* r, uint32_t addr) {
    asm volatile("ldmatrix.sync.aligned.m8n8.x4.shared.b16 {%0,%1,%2,%3}, [%4];"
                 : "=r"(r[0]), "=r"(r[1]), "=r"(r[2]), "=r"(r[3]) : "r"(addr));
}
__device__ __forceinline__ void mma_fp8(float* d, const uint32_t* a,
                                        uint32_t b0, uint32_t b1) {
    asm volatile(
        "mma.sync.aligned.m16n8k32.row.col.f32.e4m3.e4m3.f32 "
        "{%0,%1,%2,%3}, {%4,%5,%6,%7}, {%8,%9}, {%0,%1,%2,%3};"
        : "+f"(d[0]), "+f"(d[1]), "+f"(d[2]), "+f"(d[3])
        : "r"(a[0]), "r"(a[1]), "r"(a[2]), "r"(a[3]), "r"(b0), "r"(b1));
}

__device__ __forceinline__ ushort4 cvt8_e4m3(float4 a0, float4 a1) {
    ushort4 u;
    u.x = __nv_cvt_float2_to_fp8x2(make_float2(a0.x, a0.y), __NV_SATFINITE, __NV_E4M3);
    u.y = __nv_cvt_float2_to_fp8x2(make_float2(a0.z, a0.w), __NV_SATFINITE, __NV_E4M3);
    u.z = __nv_cvt_float2_to_fp8x2(make_float2(a1.x, a1.y), __NV_SATFINITE, __NV_E4M3);
    u.w = __nv_cvt_float2_to_fp8x2(make_float2(a1.z, a1.w), __NV_SATFINITE, __NV_E4M3);
    return u;
}

// ---------------- merged prep kernel -----------------------------------------
__global__ __launch_bounds__(256) void conv_all(const float* __restrict__ x,
                                                const float* __restrict__ c,
                                                const float* __restrict__ ls,
                                                const float* __restrict__ w) {
    const int lane = threadIdx.x & 31;
    if (blockIdx.x < 8192) {
        int row = blockIdx.x * 8 + (threadIdx.x >> 5);
        const float* r = x + (size_t)row * IN_DIM;
        int k0 = lane * 8;
        float4 a0 = *(const float4*)(r + k0);
        float4 a1 = *(const float4*)(r + k0 + 4);
        float ss = a0.x*a0.x + a0.y*a0.y + a0.z*a0.z + a0.w*a0.w +
                   a1.x*a1.x + a1.y*a1.y + a1.z*a1.z + a1.w*a1.w;
#pragma unroll
        for (int o = 16; o > 0; o >>= 1) ss += __shfl_xor_sync(0xffffffffu, ss, o);
        if (lane == 0) g_xsq[row] = ss;
        *(ushort4*)(g_x8 + (size_t)row * IN_DIM + k0) = cvt8_e4m3(a0, a1);
    } else if (blockIdx.x < 8256) {
        int g = (blockIdx.x - 8192) * 8 + (threadIdx.x >> 5);
        const float* r = c + (size_t)g * IN_DIM;
        int k0 = lane * 8;
        float4 a0 = *(const float4*)(r + k0);
        float4 a1 = *(const float4*)(r + k0 + 4);
        float ss = a0.x*a0.x + a0.y*a0.y + a0.z*a0.z + a0.w*a0.w +
                   a1.x*a1.x + a1.y*a1.y + a1.z*a1.z + a1.w*a1.w;
#pragma unroll
        for (int o = 16; o > 0; o >>= 1) ss += __shfl_xor_sync(0xffffffffu, ss, o);
        if (lane == 0) { g_csq[g] = ss; g_s[g] = expf(ls[g]); }
        *(ushort4*)(g_c8 + (size_t)g * IN_DIM + k0) = cvt8_e4m3(a0, a1);
    } else {
        int wr = (blockIdx.x - 8256) * 8 + (threadIdx.x >> 5);
        const float* r = w + (size_t)wr * G_DIM;
#pragma unroll
        for (int part = 0; part < 2; part++) {
            int k0 = lane * 16 + part * 8;
            float4 a0 = *(const float4*)(r + k0);
            float4 a1 = *(const float4*)(r + k0 + 4);
            __nv_bfloat162 h0 = __floats2bfloat162_rn(a0.x, a0.y);
            __nv_bfloat162 h1 = __floats2bfloat162_rn(a0.z, a0.w);
            __nv_bfloat162 h2 = __floats2bfloat162_rn(a1.x, a1.y);
            __nv_bfloat162 h3 = __floats2bfloat162_rn(a1.z, a1.w);
            *(uint4*)(g_wb + (size_t)wr * G_DIM + k0) =
                make_uint4(*(uint32_t*)&h0, *(uint32_t*)&h1, *(uint32_t*)&h2, *(uint32_t*)&h3);
        }
    }
}

// ---------------- fused RBF-GEMM + block-sparse GEMM2 + LN + tanh ------------
// Persistent: 148 CTAs x 512 threads. Centers (512x256B fp8) resident in SMEM.
// Grid-stride over 1024 tiles of 64 rows; per tile: fp8 MMA 64x512x256,
// RBF epilogue -> local zero flags -> fast-path broadcast store (or exact
// SIMT slow path for any nonzero tile).
#define PB 272
#define SM_B 0
#define SM_A (512 * PB)                       // two 64-row A buffers
#define SM_F (SM_A + 2 * 64 * PB)             // float section (bytes)
#define F_SMEM (SM_F + (512 * 6 + 32 + 8) * 4)
#define NT (B_ROWS / 64)

__global__ __launch_bounds__(512, 1) void fused_kan(const float* __restrict__ bias,
                                                    const float* __restrict__ gamma,
                                                    const float* __restrict__ beta,
                                                    float* __restrict__ out) {
    extern __shared__ __align__(16) uint8_t sm[];
    float* s_cq  = (float*)(sm + SM_F);
    float* s_cs  = s_cq + 512;
    float* vs_b  = s_cs + 512;
    float* vs_g  = vs_b + 512;
    float* vs_be = vs_g + 512;
    float* ybuf  = vs_be + 512;
    float* red   = ybuf + 512;        // 32 floats
    int*   s_fl  = (int*)(red + 32);  // 8 chunk flags

    const int tid = threadIdx.x, lane = tid & 31, wid = tid >> 5;
    const uint32_t sbase = smem_cast(sm);

    s_cq[tid] = g_csq[tid]; s_cs[tid] = g_s[tid];
    vs_b[tid] = bias[tid];  vs_g[tid] = gamma[tid]; vs_be[tid] = beta[tid];

    // load centers (512 x 256B) into resident SMEM: 16 cp16/thread
#pragma unroll
    for (int i = 0; i < 16; i++) {
        const int v = tid + i * 512;
        const int row = v >> 4, cb = (v & 15) * 16;
        cp16(sbase + (uint32_t)(row * PB + cb), g_c8 + (size_t)row * IN_DIM + cb);
    }
    CP_COMMIT();
    __syncthreads();

    // once per CTA: ybuf = tanh(LN(bias))
    {
        const float v = vs_b[tid];
        float s = v, q = v * v;
#pragma unroll
        for (int o = 16; o > 0; o >>= 1) {
            s += __shfl_xor_sync(0xffffffffu, s, o);
            q += __shfl_xor_sync(0xffffffffu, q, o);
        }
        if (lane == 0) { red[wid] = s; red[wid + 16] = q; }
        __syncthreads();
        if (tid == 0) {
            float ts = 0.f, tq = 0.f;
#pragma unroll
            for (int w = 0; w < 16; w++) { ts += red[w]; tq += red[w + 16]; }
            const float mean = ts * (1.0f / 512.0f);
            const float var  = tq * (1.0f / 512.0f) - mean * mean;
            red[0] = mean; red[1] = rsqrtf(var + LN_EPS);
        }
        __syncthreads();
        ybuf[tid] = tanhf((v - red[0]) * red[1] * vs_g[tid] + vs_be[tid]);
    }
    __syncthreads();

    // A-tile loader: 64 rows x 256B = 2 cp16/thread
    auto loadA = [&](int tile, int buf) {
#pragma unroll
        for (int i = 0; i < 2; i++) {
            const int v = tid + i * 512;
            const int row = v >> 4, cb = (v & 15) * 16;
            cp16(sbase + (uint32_t)(SM_A + buf * 64 * PB + row * PB + cb),
                 g_x8 + (size_t)(tile * 64 + row) * IN_DIM + cb);
        }
    };

    const int wr = wid >> 3, wc = wid & 7;        // warp grid 2 x 8
    const int arow = lane & 15, acolb = (lane >> 4) * 16;
    const int brow = (lane & 7) | ((lane & 16) >> 1), bcolb = (lane & 8) * 2;
    const int erow = lane >> 2, ecol = (lane & 3) * 2;

    int buf = 0;
    if (blockIdx.x < NT) { loadA(blockIdx.x, 0); }
    CP_COMMIT();

    for (int tile = blockIdx.x; tile < NT; tile += 148) {
        const int bm = tile * 64;
        CP_WAIT(0);
        if (tid < 8) s_fl[tid] = 0;
        __syncthreads();
        if (tile + 148 < NT) loadA(tile + 148, buf ^ 1);
        CP_COMMIT();

        // ---------- MMA: 64 x 512 x 256, fp8 ----------
        float acc[2][8][4] = {};
        const uint32_t abase = sbase + (uint32_t)(SM_A + buf * 64 * PB);
#pragma unroll
        for (int kk = 0; kk < 8; kk++) {
            uint32_t af[2][4], bfr[4][4];
#pragma unroll
            for (int mf = 0; mf < 2; mf++)
                ldsm4(af[mf], abase + (uint32_t)((wr * 32 + mf * 16 + arow) * PB +
                                                 kk * 32 + acolb));
#pragma unroll
            for (int nh = 0; nh < 4; nh++)
                ldsm4(bfr[nh], sbase + (uint32_t)((wc * 64 + nh * 16 + brow) * PB +
                                                  kk * 32 + bcolb));
#pragma unroll
            for (int mf = 0; mf < 2; mf++)
#pragma unroll
                for (int nf = 0; nf < 8; nf++)
                    mma_fp8(acc[mf][nf], af[mf],
                            bfr[nf >> 1][(nf & 1) * 2], bfr[nf >> 1][(nf & 1) * 2 + 1]);
        }

        // ---------- RBF epilogue: exp(-(xq+cq-2cross)*s), flags, pred stores --
        uint32_t nzu = 0;
#pragma unroll
        for (int mf = 0; mf < 2; mf++) {
            const int gm0 = bm + wr * 32 + mf * 16 + erow;
            const float xq0 = g_xsq[gm0], xq1 = g_xsq[gm0 + 8];
#pragma unroll
            for (int nf = 0; nf < 8; nf++) {
                const int gc = wc * 64 + nf * 8 + ecol;
                const float cq0 = s_cq[gc], ss0 = s_cs[gc];
                const float cq1 = s_cq[gc + 1], ss1 = s_cs[gc + 1];
                float v00 = __expf((2.f * acc[mf][nf][0] - xq0 - cq0) * ss0);
                float v01 = __expf((2.f * acc[mf][nf][1] - xq0 - cq1) * ss1);
                float v10 = __expf((2.f * acc[mf][nf][2] - xq1 - cq0) * ss0);
                float v11 = __expf((2.f * acc[mf][nf][3] - xq1 - cq1) * ss1);
                __nv_bfloat162 h0 = __floats2bfloat162_rn(v00, v01);
                __nv_bfloat162 h1 = __floats2bfloat162_rn(v10, v11);
                const uint32_t p0 = *(uint32_t*)&h0, p1 = *(uint32_t*)&h1;
                nzu |= p0 | p1;
                if (p0) *(uint32_t*)(g_scaled + (size_t)gm0 * G_DIM + gc) = p0;
                if (p1) *(uint32_t*)(g_scaled + (size_t)(gm0 + 8) * G_DIM + gc) = p1;
            }
        }
        nzu = __reduce_or_sync(0xffffffffu, nzu);
        if (lane == 0 && nzu) atomicOr(&s_fl[wc], 1);
        __syncthreads();

        int nz = 0;
#pragma unroll
        for (int k = 0; k < 8; k++) nz |= s_fl[k];

        if (nz == 0) {
            // ---------- fast path: broadcast ybuf to 64 rows ----------
            const float4* y4 = (const float4*)ybuf;
            float4* o4 = (float4*)(out + (size_t)bm * W_DIM);
#pragma unroll
            for (int i = 0; i < 16; i++) {
                const int idx = tid + i * 512;
                __stcs(o4 + idx, y4[idx & 127]);
            }
        } else {
            // ---------- slow path: exact SIMT GEMM2 + LN (rarely/never taken) -
            int fl[8];
#pragma unroll
            for (int k = 0; k < 8; k++) fl[k] = s_fl[k];
            for (int r = 0; r < 64; r++) {
                float a = vs_b[tid];
                for (int i = 0; i < 8; i++) {
                    if (!fl[i]) continue;
                    for (int j = 0; j < 64; j++) {
                        const int g = i * 64 + j;
                        a += __bfloat162float(g_scaled[(size_t)(bm + r) * G_DIM + g]) *
                             __bfloat162float(g_wb[(size_t)tid * G_DIM + g]);
                    }
                }
                float s = a, q = a * a;
#pragma unroll
                for (int o = 16; o > 0; o >>= 1) {
                    s += __shfl_xor_sync(0xffffffffu, s, o);
                    q += __shfl_xor_sync(0xffffffffu, q, o);
                }
                if (lane == 0) { red[wid] = s; red[wid + 16] = q; }
                __syncthreads();
                if (tid == 0) {
                    float ts = 0.f, tq = 0.f;
#pragma unroll
                    for (int w = 0; w < 16; w++) { ts += red[w]; tq += red[w + 16]; }
                    const float mean = ts * (1.0f / 512.0f);
                    const float var  = tq * (1.0f / 512.0f) - mean * mean;
                    red[0] = mean; red[1] = rsqrtf(var + LN_EPS);
                }
                __syncthreads();
                out[(size_t)(bm + r) * W_DIM + tid] =
                    tanhf((a - red[0]) * red[1] * vs_g[tid] + vs_be[tid]);
                __syncthreads();
            }
        }
        buf ^= 1;
        __syncthreads();   // all threads done with s_fl/stores before next tile
    }
}

// ---------------------------------------------------------------------------
extern "C" void kernel_launch(void* const* d_in, const int* in_sizes, int n_in,
                              void* d_out, int out_size) {
    const float* inputs     = (const float*)d_in[0];
    const float* centers    = (const float*)d_in[1];
    const float* log_scales = (const float*)d_in[2];
    const float* W_mix      = (const float*)d_in[3];
    const float* b_mix      = (const float*)d_in[4];
    const float* ln_gamma   = (const float*)d_in[5];
    const float* ln_beta    = (const float*)d_in[6];
    float* out = (float*)d_out;

    cudaFuncSetAttribute(fused_kan, cudaFuncAttributeMaxDynamicSharedMemorySize, F_SMEM);

    conv_all<<<8320, 256>>>(inputs, centers, log_scales, W_mix);
    fused_kan<<<148, 512, F_SMEM>>>(b_mix, ln_gamma, ln_beta, out);
}

// round 15
// speedup vs baseline: 1.9945x; 1.0744x over previous
#include <cuda_runtime.h>
#include <cuda_bf16.h>
#include <cuda_fp8.h>
#include <math.h>
#include <stdint.h>

#define B_ROWS 65536
#define IN_DIM 256
#define G_DIM  512
#define W_DIM  512
#define LN_EPS 1e-5f

// ---------------- global scratch (device globals; no allocs) ----------------
__device__ uint8_t g_x8[(size_t)B_ROWS * IN_DIM];          // inputs e4m3
__device__ uint8_t g_c8[(size_t)G_DIM * IN_DIM];           // centers e4m3
__device__ __nv_bfloat16 g_wb[(size_t)W_DIM * G_DIM];      // W_mix bf16
__device__ __nv_bfloat16 g_scaled[(size_t)B_ROWS * G_DIM]; // RBF activations bf16
__device__ float g_xsq[B_ROWS];
__device__ float g_csq[G_DIM];
__device__ float g_s[G_DIM];

// ---------------- PTX helpers (sm_80/89+ subset; compute_103-safe) ----------
__device__ __forceinline__ uint32_t smem_cast(const void* p) {
    return (uint32_t)__cvta_generic_to_shared(p);
}
__device__ __forceinline__ void cp16(uint32_t dst, const void* src) {
    asm volatile("cp.async.cg.shared.global [%0], [%1], 16;" :: "r"(dst), "l"(src));
}
#define CP_COMMIT() asm volatile("cp.async.commit_group;" ::: "memory")
#define CP_WAIT(n)  asm volatile("cp.async.wait_group %0;" :: "n"(n) : "memory")

__device__ __forceinline__ void ldsm4(uint32_t* r, uint32_t addr) {
    asm volatile("ldmatrix.sync.aligned.m8n8.x4.shared.b16 {%0,%1,%2,%3}, [%4];"
                 : "=r"(r[0]), "=r"(r[1]), "=r"(r[2]), "=r"(r[3]) : "r"(addr));
}
__device__ __forceinline__ void mma_fp8(float* d, const uint32_t* a,
                                        uint32_t b0, uint32_t b1) {
    asm volatile(
        "mma.sync.aligned.m16n8k32.row.col.f32.e4m3.e4m3.f32 "
        "{%0,%1,%2,%3}, {%4,%5,%6,%7}, {%8,%9}, {%0,%1,%2,%3};"
        : "+f"(d[0]), "+f"(d[1]), "+f"(d[2]), "+f"(d[3])
        : "r"(a[0]), "r"(a[1]), "r"(a[2]), "r"(a[3]), "r"(b0), "r"(b1));
}

__device__ __forceinline__ ushort4 cvt8_e4m3(float4 a0, float4 a1) {
    ushort4 u;
    u.x = __nv_cvt_float2_to_fp8x2(make_float2(a0.x, a0.y), __NV_SATFINITE, __NV_E4M3);
    u.y = __nv_cvt_float2_to_fp8x2(make_float2(a0.z, a0.w), __NV_SATFINITE, __NV_E4M3);
    u.z = __nv_cvt_float2_to_fp8x2(make_float2(a1.x, a1.y), __NV_SATFINITE, __NV_E4M3);
    u.w = __nv_cvt_float2_to_fp8x2(make_float2(a1.z, a1.w), __NV_SATFINITE, __NV_E4M3);
    return u;
}

// ---------------- merged prep kernel -----------------------------------------
__global__ __launch_bounds__(256) void conv_all(const float* __restrict__ x,
                                                const float* __restrict__ c,
                                                const float* __restrict__ ls,
                                                const float* __restrict__ w) {
    const int lane = threadIdx.x & 31;
    if (blockIdx.x < 8192) {
        int row = blockIdx.x * 8 + (threadIdx.x >> 5);
        const float* r = x + (size_t)row * IN_DIM;
        int k0 = lane * 8;
        float4 a0 = *(const float4*)(r + k0);
        float4 a1 = *(const float4*)(r + k0 + 4);
        float ss = a0.x*a0.x + a0.y*a0.y + a0.z*a0.z + a0.w*a0.w +
                   a1.x*a1.x + a1.y*a1.y + a1.z*a1.z + a1.w*a1.w;
#pragma unroll
        for (int o = 16; o > 0; o >>= 1) ss += __shfl_xor_sync(0xffffffffu, ss, o);
        if (lane == 0) g_xsq[row] = ss;
        *(ushort4*)(g_x8 + (size_t)row * IN_DIM + k0) = cvt8_e4m3(a0, a1);
    } else if (blockIdx.x < 8256) {
        int g = (blockIdx.x - 8192) * 8 + (threadIdx.x >> 5);
        const float* r = c + (size_t)g * IN_DIM;
        int k0 = lane * 8;
        float4 a0 = *(const float4*)(r + k0);
        float4 a1 = *(const float4*)(r + k0 + 4);
        float ss = a0.x*a0.x + a0.y*a0.y + a0.z*a0.z + a0.w*a0.w +
                   a1.x*a1.x + a1.y*a1.y + a1.z*a1.z + a1.w*a1.w;
#pragma unroll
        for (int o = 16; o > 0; o >>= 1) ss += __shfl_xor_sync(0xffffffffu, ss, o);
        if (lane == 0) { g_csq[g] = ss; g_s[g] = expf(ls[g]); }
        *(ushort4*)(g_c8 + (size_t)g * IN_DIM + k0) = cvt8_e4m3(a0, a1);
    } else {
        int wr = (blockIdx.x - 8256) * 8 + (threadIdx.x >> 5);
        const float* r = w + (size_t)wr * G_DIM;
#pragma unroll
        for (int part = 0; part < 2; part++) {
            int k0 = lane * 16 + part * 8;
            float4 a0 = *(const float4*)(r + k0);
            float4 a1 = *(const float4*)(r + k0 + 4);
            __nv_bfloat162 h0 = __floats2bfloat162_rn(a0.x, a0.y);
            __nv_bfloat162 h1 = __floats2bfloat162_rn(a0.z, a0.w);
            __nv_bfloat162 h2 = __floats2bfloat162_rn(a1.x, a1.y);
            __nv_bfloat162 h3 = __floats2bfloat162_rn(a1.z, a1.w);
            *(uint4*)(g_wb + (size_t)wr * G_DIM + k0) =
                make_uint4(*(uint32_t*)&h0, *(uint32_t*)&h1, *(uint32_t*)&h2, *(uint32_t*)&h3);
        }
    }
}

// ---------------- fused RBF-GEMM + block-sparse GEMM2 + LN + tanh ------------
// Persistent: 148 CTAs x 512 threads. Centers (512x256B fp8) resident in SMEM.
// Per tile: fp8 MMA 64x512x256 -> RBF args -> warp-max threshold gate
// (exp(arg) rounds to bf16 zero iff arg < -92.87; skip exp/store when the
// whole warp is below -93) -> fast-path broadcast store / exact slow path.
#define PB 272
#define SM_A (512 * PB)                       // two 64-row A buffers
#define SM_F (SM_A + 2 * 64 * PB)             // float section (bytes)
#define F_SMEM (SM_F + (512 * 6 + 32 + 8) * 4)
#define NT (B_ROWS / 64)

__global__ __launch_bounds__(512, 1) void fused_kan(const float* __restrict__ bias,
                                                    const float* __restrict__ gamma,
                                                    const float* __restrict__ beta,
                                                    float* __restrict__ out) {
    extern __shared__ __align__(16) uint8_t sm[];
    float* s_cq  = (float*)(sm + SM_F);
    float* s_cs  = s_cq + 512;
    float* vs_b  = s_cs + 512;
    float* vs_g  = vs_b + 512;
    float* vs_be = vs_g + 512;
    float* ybuf  = vs_be + 512;
    float* red   = ybuf + 512;        // 32 floats
    int*   s_fl  = (int*)(red + 32);  // 8 chunk flags

    const int tid = threadIdx.x, lane = tid & 31, wid = tid >> 5;
    const uint32_t sbase = smem_cast(sm);

    s_cq[tid] = g_csq[tid]; s_cs[tid] = g_s[tid];
    vs_b[tid] = bias[tid];  vs_g[tid] = gamma[tid]; vs_be[tid] = beta[tid];

    // load centers (512 x 256B) into resident SMEM: 16 cp16/thread
#pragma unroll
    for (int i = 0; i < 16; i++) {
        const int v = tid + i * 512;
        const int row = v >> 4, cb = (v & 15) * 16;
        cp16(sbase + (uint32_t)(row * PB + cb), g_c8 + (size_t)row * IN_DIM + cb);
    }
    CP_COMMIT();
    __syncthreads();

    // once per CTA: ybuf = tanh(LN(bias))
    {
        const float v = vs_b[tid];
        float s = v, q = v * v;
#pragma unroll
        for (int o = 16; o > 0; o >>= 1) {
            s += __shfl_xor_sync(0xffffffffu, s, o);
            q += __shfl_xor_sync(0xffffffffu, q, o);
        }
        if (lane == 0) { red[wid] = s; red[wid + 16] = q; }
        __syncthreads();
        if (tid == 0) {
            float ts = 0.f, tq = 0.f;
#pragma unroll
            for (int w = 0; w < 16; w++) { ts += red[w]; tq += red[w + 16]; }
            const float mean = ts * (1.0f / 512.0f);
            const float var  = tq * (1.0f / 512.0f) - mean * mean;
            red[0] = mean; red[1] = rsqrtf(var + LN_EPS);
        }
        __syncthreads();
        ybuf[tid] = tanhf((v - red[0]) * red[1] * vs_g[tid] + vs_be[tid]);
    }
    __syncthreads();

    // A-tile loader: 64 rows x 256B = 2 cp16/thread
    auto loadA = [&](int tile, int buf) {
#pragma unroll
        for (int i = 0; i < 2; i++) {
            const int v = tid + i * 512;
            const int row = v >> 4, cb = (v & 15) * 16;
            cp16(sbase + (uint32_t)(SM_A + buf * 64 * PB + row * PB + cb),
                 g_x8 + (size_t)(tile * 64 + row) * IN_DIM + cb);
        }
    };

    const int wr = wid >> 3, wc = wid & 7;        // warp grid 2 x 8
    const int arow = lane & 15, acolb = (lane >> 4) * 16;
    const int brow = (lane & 7) | ((lane & 16) >> 1), bcolb = (lane & 8) * 2;
    const int erow = lane >> 2, ecol = (lane & 3) * 2;

    int buf = 0;
    if (blockIdx.x < NT) { loadA(blockIdx.x, 0); }
    CP_COMMIT();

    for (int tile = blockIdx.x; tile < NT; tile += 148) {
        const int bm = tile * 64;
        CP_WAIT(0);
        if (tid < 8) s_fl[tid] = 0;
        __syncthreads();
        if (tile + 148 < NT) loadA(tile + 148, buf ^ 1);
        CP_COMMIT();

        // ---------- MMA: 64 x 512 x 256, fp8 ----------
        float acc[2][8][4] = {};
        const uint32_t abase = sbase + (uint32_t)(SM_A + buf * 64 * PB);
#pragma unroll
        for (int kk = 0; kk < 8; kk++) {
            uint32_t af[2][4], bfr[4][4];
#pragma unroll
            for (int mf = 0; mf < 2; mf++)
                ldsm4(af[mf], abase + (uint32_t)((wr * 32 + mf * 16 + arow) * PB +
                                                 kk * 32 + acolb));
#pragma unroll
            for (int nh = 0; nh < 4; nh++)
                ldsm4(bfr[nh], sbase + (uint32_t)((wc * 64 + nh * 16 + brow) * PB +
                                                  kk * 32 + bcolb));
#pragma unroll
            for (int mf = 0; mf < 2; mf++)
#pragma unroll
                for (int nf = 0; nf < 8; nf++)
                    mma_fp8(acc[mf][nf], af[mf],
                            bfr[nf >> 1][(nf & 1) * 2], bfr[nf >> 1][(nf & 1) * 2 + 1]);
        }

        // ---------- RBF epilogue with threshold gate ----------
        // arg = (2*cross - xq - cq) * s ; exp(arg) rounds to bf16 0 iff arg < -92.87
        float tmax = -1e30f;
#pragma unroll
        for (int mf = 0; mf < 2; mf++) {
            const int gm0 = bm + wr * 32 + mf * 16 + erow;
            const float xq0 = g_xsq[gm0], xq1 = g_xsq[gm0 + 8];
#pragma unroll
            for (int nf = 0; nf < 8; nf++) {
                const int gc = wc * 64 + nf * 8 + ecol;
                const float cq0 = s_cq[gc], ss0 = s_cs[gc];
                const float cq1 = s_cq[gc + 1], ss1 = s_cs[gc + 1];
                acc[mf][nf][0] = (2.f * acc[mf][nf][0] - xq0 - cq0) * ss0;
                acc[mf][nf][1] = (2.f * acc[mf][nf][1] - xq0 - cq1) * ss1;
                acc[mf][nf][2] = (2.f * acc[mf][nf][2] - xq1 - cq0) * ss0;
                acc[mf][nf][3] = (2.f * acc[mf][nf][3] - xq1 - cq1) * ss1;
                tmax = fmaxf(tmax, fmaxf(fmaxf(acc[mf][nf][0], acc[mf][nf][1]),
                                         fmaxf(acc[mf][nf][2], acc[mf][nf][3])));
            }
        }
#pragma unroll
        for (int o = 16; o > 0; o >>= 1)
            tmax = fmaxf(tmax, __shfl_xor_sync(0xffffffffu, tmax, o));

        if (tmax >= -93.0f) {   // at least one value may survive bf16 rounding
            uint32_t nzu = 0;
#pragma unroll
            for (int mf = 0; mf < 2; mf++) {
                const int gm0 = bm + wr * 32 + mf * 16 + erow;
#pragma unroll
                for (int nf = 0; nf < 8; nf++) {
                    const int gc = wc * 64 + nf * 8 + ecol;
                    float v00 = __expf(acc[mf][nf][0]);
                    float v01 = __expf(acc[mf][nf][1]);
                    float v10 = __expf(acc[mf][nf][2]);
                    float v11 = __expf(acc[mf][nf][3]);
                    __nv_bfloat162 h0 = __floats2bfloat162_rn(v00, v01);
                    __nv_bfloat162 h1 = __floats2bfloat162_rn(v10, v11);
                    const uint32_t p0 = *(uint32_t*)&h0, p1 = *(uint32_t*)&h1;
                    nzu |= p0 | p1;
                    if (p0) *(uint32_t*)(g_scaled + (size_t)gm0 * G_DIM + gc) = p0;
                    if (p1) *(uint32_t*)(g_scaled + (size_t)(gm0 + 8) * G_DIM + gc) = p1;
                }
            }
            nzu = __reduce_or_sync(0xffffffffu, nzu);
            if (lane == 0 && nzu) atomicOr(&s_fl[wc], 1);
        }
        __syncthreads();

        int nz = 0;
#pragma unroll
        for (int k = 0; k < 8; k++) nz |= s_fl[k];

        if (nz == 0) {
            // ---------- fast path: broadcast ybuf to 64 rows ----------
            const float4* y4 = (const float4*)ybuf;
            float4* o4 = (float4*)(out + (size_t)bm * W_DIM);
#pragma unroll
            for (int i = 0; i < 16; i++) {
                const int idx = tid + i * 512;
                __stcs(o4 + idx, y4[idx & 127]);
            }
        } else {
            // ---------- slow path: exact SIMT GEMM2 + LN (rarely taken) ------
            int fl[8];
#pragma unroll
            for (int k = 0; k < 8; k++) fl[k] = s_fl[k];
            for (int r = 0; r < 64; r++) {
                float a = vs_b[tid];
                for (int i = 0; i < 8; i++) {
                    if (!fl[i]) continue;
                    for (int j = 0; j < 64; j++) {
                        const int g = i * 64 + j;
                        a += __bfloat162float(g_scaled[(size_t)(bm + r) * G_DIM + g]) *
                             __bfloat162float(g_wb[(size_t)tid * G_DIM + g]);
                    }
                }
                float s = a, q = a * a;
#pragma unroll
                for (int o = 16; o > 0; o >>= 1) {
                    s += __shfl_xor_sync(0xffffffffu, s, o);
                    q += __shfl_xor_sync(0xffffffffu, q, o);
                }
                if (lane == 0) { red[wid] = s; red[wid + 16] = q; }
                __syncthreads();
                if (tid == 0) {
                    float ts = 0.f, tq = 0.f;
#pragma unroll
                    for (int w = 0; w < 16; w++) { ts += red[w]; tq += red[w + 16]; }
                    const float mean = ts * (1.0f / 512.0f);
                    const float var  = tq * (1.0f / 512.0f) - mean * mean;
                    red[0] = mean; red[1] = rsqrtf(var + LN_EPS);
                }
                __syncthreads();
                out[(size_t)(bm + r) * W_DIM + tid] =
                    tanhf((a - red[0]) * red[1] * vs_g[tid] + vs_be[tid]);
                __syncthreads();
            }
        }
        buf ^= 1;
        __syncthreads();   // all threads done with s_fl/stores before next tile
    }
}

// ---------------------------------------------------------------------------
extern "C" void kernel_launch(void* const* d_in, const int* in_sizes, int n_in,
                              void* d_out, int out_size) {
    const float* inputs     = (const float*)d_in[0];
    const float* centers    = (const float*)d_in[1];
    const float* log_scales = (const float*)d_in[2];
    const float* W_mix      = (const float*)d_in[3];
    const float* b_mix      = (const float*)d_in[4];
    const float* ln_gamma   = (const float*)d_in[5];
    const float* ln_beta    = (const float*)d_in[6];
    float* out = (float*)d_out;

    cudaFuncSetAttribute(fused_kan, cudaFuncAttributeMaxDynamicSharedMemorySize, F_SMEM);

    conv_all<<<8320, 256>>>(inputs, centers, log_scales, W_mix);
    fused_kan<<<148, 512, F_SMEM>>>(b_mix, ln_gamma, ln_beta, out);
}

// round 16
// speedup vs baseline: 2.0584x; 1.0321x over previous
#include <cuda_runtime.h>
#include <cuda_bf16.h>
#include <cuda_fp8.h>
#include <math.h>
#include <stdint.h>

#define B_ROWS 65536
#define IN_DIM 256
#define G_DIM  512
#define W_DIM  512
#define LN_EPS 1e-5f

// ---------------- global scratch (device globals; no allocs) ----------------
__device__ uint8_t g_c8[(size_t)G_DIM * IN_DIM];           // centers e4m3
__device__ __nv_bfloat16 g_wb[(size_t)W_DIM * G_DIM];      // W_mix bf16
__device__ __nv_bfloat16 g_scaled[(size_t)B_ROWS * G_DIM]; // RBF activations bf16
__device__ float g_csq[G_DIM];
__device__ float g_s[G_DIM];

// ---------------- PTX helpers (sm_80/89+ subset; compute_103-safe) ----------
__device__ __forceinline__ uint32_t smem_cast(const void* p) {
    return (uint32_t)__cvta_generic_to_shared(p);
}
__device__ __forceinline__ void cp16(uint32_t dst, const void* src) {
    asm volatile("cp.async.cg.shared.global [%0], [%1], 16;" :: "r"(dst), "l"(src));
}
#define CP_COMMIT() asm volatile("cp.async.commit_group;" ::: "memory")
#define CP_WAIT(n)  asm volatile("cp.async.wait_group %0;" :: "n"(n) : "memory")

__device__ __forceinline__ void ldsm4(uint32_t* r, uint32_t addr) {
    asm volatile("ldmatrix.sync.aligned.m8n8.x4.shared.b16 {%0,%1,%2,%3}, [%4];"
                 : "=r"(r[0]), "=r"(r[1]), "=r"(r[2]), "=r"(r[3]) : "r"(addr));
}
__device__ __forceinline__ void mma_fp8(float* d, const uint32_t* a,
                                        uint32_t b0, uint32_t b1) {
    asm volatile(
        "mma.sync.aligned.m16n8k32.row.col.f32.e4m3.e4m3.f32 "
        "{%0,%1,%2,%3}, {%4,%5,%6,%7}, {%8,%9}, {%0,%1,%2,%3};"
        : "+f"(d[0]), "+f"(d[1]), "+f"(d[2]), "+f"(d[3])
        : "r"(a[0]), "r"(a[1]), "r"(a[2]), "r"(a[3]), "r"(b0), "r"(b1));
}

__device__ __forceinline__ ushort4 cvt8_e4m3(float4 a0, float4 a1) {
    ushort4 u;
    u.x = __nv_cvt_float2_to_fp8x2(make_float2(a0.x, a0.y), __NV_SATFINITE, __NV_E4M3);
    u.y = __nv_cvt_float2_to_fp8x2(make_float2(a0.z, a0.w), __NV_SATFINITE, __NV_E4M3);
    u.z = __nv_cvt_float2_to_fp8x2(make_float2(a1.x, a1.y), __NV_SATFINITE, __NV_E4M3);
    u.w = __nv_cvt_float2_to_fp8x2(make_float2(a1.z, a1.w), __NV_SATFINITE, __NV_E4M3);
    return u;
}

// ---------------- prep kernel: centers + W only ------------------------------
__global__ __launch_bounds__(256) void conv_cw(const float* __restrict__ c,
                                               const float* __restrict__ ls,
                                               const float* __restrict__ w) {
    const int lane = threadIdx.x & 31;
    if (blockIdx.x < 64) {
        int g = blockIdx.x * 8 + (threadIdx.x >> 5);
        const float* r = c + (size_t)g * IN_DIM;
        int k0 = lane * 8;
        float4 a0 = *(const float4*)(r + k0);
        float4 a1 = *(const float4*)(r + k0 + 4);
        float ss = a0.x*a0.x + a0.y*a0.y + a0.z*a0.z + a0.w*a0.w +
                   a1.x*a1.x + a1.y*a1.y + a1.z*a1.z + a1.w*a1.w;
#pragma unroll
        for (int o = 16; o > 0; o >>= 1) ss += __shfl_xor_sync(0xffffffffu, ss, o);
        if (lane == 0) { g_csq[g] = ss; g_s[g] = expf(ls[g]); }
        *(ushort4*)(g_c8 + (size_t)g * IN_DIM + k0) = cvt8_e4m3(a0, a1);
    } else {
        int wr = (blockIdx.x - 64) * 8 + (threadIdx.x >> 5);
        const float* r = w + (size_t)wr * G_DIM;
#pragma unroll
        for (int part = 0; part < 2; part++) {
            int k0 = lane * 16 + part * 8;
            float4 a0 = *(const float4*)(r + k0);
            float4 a1 = *(const float4*)(r + k0 + 4);
            __nv_bfloat162 h0 = __floats2bfloat162_rn(a0.x, a0.y);
            __nv_bfloat162 h1 = __floats2bfloat162_rn(a0.z, a0.w);
            __nv_bfloat162 h2 = __floats2bfloat162_rn(a1.x, a1.y);
            __nv_bfloat162 h3 = __floats2bfloat162_rn(a1.z, a1.w);
            *(uint4*)(g_wb + (size_t)wr * G_DIM + k0) =
                make_uint4(*(uint32_t*)&h0, *(uint32_t*)&h1, *(uint32_t*)&h2, *(uint32_t*)&h3);
        }
    }
}

// ---------------- fused conv + RBF-GEMM + GEMM2 + LN + tanh ------------------
// Persistent: 148 CTAs x 512 threads. Centers fp8 resident in SMEM.
// Per tile: fp32 A rows staged via cp.async, converted to fp8 (+ xsq) between
// the two MMA half-loops of the current tile; RBF threshold-gated epilogue;
// fast-path broadcast store / exact slow path.
#define PB 272
#define SM_A (512 * PB)                       // two 64-row fp8 A buffers
#define SM_X (SM_A + 2 * 64 * PB)             // fp32 staging (32 rows, pitch 1040)
#define SM_F (SM_X + 32 * 1040)               // float section (bytes)
#define F_SMEM (SM_F + (512 * 6 + 32 + 128 + 1024 + 8) * 4)
#define NT (B_ROWS / 64)

__global__ __launch_bounds__(512, 1) void fused_kan(const float* __restrict__ xin,
                                                    const float* __restrict__ bias,
                                                    const float* __restrict__ gamma,
                                                    const float* __restrict__ beta,
                                                    float* __restrict__ out) {
    extern __shared__ __align__(16) uint8_t sm[];
    float* s_cq  = (float*)(sm + SM_F);
    float* s_cs  = s_cq + 512;
    float* vs_b  = s_cs + 512;
    float* vs_g  = vs_b + 512;
    float* vs_be = vs_g + 512;
    float* ybuf  = vs_be + 512;
    float* red   = ybuf + 512;        // 32
    float* s_xq  = red + 32;          // 2 x 64
    float* partq = s_xq + 128;        // 64 x 16 xsq partials
    int*   s_fl  = (int*)(partq + 1024);

    const int tid = threadIdx.x, lane = tid & 31, wid = tid >> 5;
    const uint32_t sbase = smem_cast(sm);

    s_cq[tid] = g_csq[tid]; s_cs[tid] = g_s[tid];
    vs_b[tid] = bias[tid];  vs_g[tid] = gamma[tid]; vs_be[tid] = beta[tid];

    // centers (512 x 256B fp8) resident: 16 cp16/thread
#pragma unroll
    for (int i = 0; i < 16; i++) {
        const int v = tid + i * 512;
        const int row = v >> 4, cb = (v & 15) * 16;
        cp16(sbase + (uint32_t)(row * PB + cb), g_c8 + (size_t)row * IN_DIM + cb);
    }
    CP_COMMIT();
    __syncthreads();

    // once per CTA: ybuf = tanh(LN(bias))
    {
        const float v = vs_b[tid];
        float s = v, q = v * v;
#pragma unroll
        for (int o = 16; o > 0; o >>= 1) {
            s += __shfl_xor_sync(0xffffffffu, s, o);
            q += __shfl_xor_sync(0xffffffffu, q, o);
        }
        if (lane == 0) { red[wid] = s; red[wid + 16] = q; }
        __syncthreads();
        if (tid == 0) {
            float ts = 0.f, tq = 0.f;
#pragma unroll
            for (int w = 0; w < 16; w++) { ts += red[w]; tq += red[w + 16]; }
            const float mean = ts * (1.0f / 512.0f);
            const float var  = tq * (1.0f / 512.0f) - mean * mean;
            red[0] = mean; red[1] = rsqrtf(var + LN_EPS);
        }
        __syncthreads();
        ybuf[tid] = tanhf((v - red[0]) * red[1] * vs_g[tid] + vs_be[tid]);
    }
    __syncthreads();

    // stage one 32-row fp32 chunk of tile `t`, half h: 4 cp16/thread
    auto stageX = [&](int t, int h) {
#pragma unroll
        for (int i = 0; i < 4; i++) {
            const int idx = tid + i * 512;           // 0..2047
            const int row = idx >> 6, c16 = idx & 63;
            cp16(sbase + (uint32_t)(SM_X + row * 1040 + c16 * 16),
                 xin + ((size_t)(t * 64 + h * 32 + row) * IN_DIM + c16 * 4));
        }
        CP_COMMIT();
    };
    // convert staged chunk h into fp8 A-buffer `db` + xsq partials
    auto convX = [&](int h, int db) {
        const int row = tid & 31, seg = tid >> 5;    // conflict-free phase tiling
        const uint32_t src = sbase + (uint32_t)(SM_X + row * 1040 + seg * 64);
        float4 f0 = *(const float4*)(sm + SM_X + row * 1040 + seg * 64);
        float4 f1 = *(const float4*)(sm + SM_X + row * 1040 + seg * 64 + 16);
        float4 f2 = *(const float4*)(sm + SM_X + row * 1040 + seg * 64 + 32);
        float4 f3 = *(const float4*)(sm + SM_X + row * 1040 + seg * 64 + 48);
        (void)src;
        ushort4 ua = cvt8_e4m3(f0, f1);
        ushort4 ub = cvt8_e4m3(f2, f3);
        uint4 wv;
        wv.x = (uint32_t)ua.x | ((uint32_t)ua.y << 16);
        wv.y = (uint32_t)ua.z | ((uint32_t)ua.w << 16);
        wv.z = (uint32_t)ub.x | ((uint32_t)ub.y << 16);
        wv.w = (uint32_t)ub.z | ((uint32_t)ub.w << 16);
        *(uint4*)(sm + SM_A + db * 64 * PB + (h * 32 + row) * PB + seg * 16) = wv;
        float ss = f0.x*f0.x + f0.y*f0.y + f0.z*f0.z + f0.w*f0.w +
                   f1.x*f1.x + f1.y*f1.y + f1.z*f1.z + f1.w*f1.w +
                   f2.x*f2.x + f2.y*f2.y + f2.z*f2.z + f2.w*f2.w +
                   f3.x*f3.x + f3.y*f3.y + f3.z*f3.z + f3.w*f3.w;
        partq[(h * 32 + row) * 16 + seg] = ss;
    };

    const int wr = wid >> 3, wc = wid & 7;        // warp grid 2 x 8
    const int arow = lane & 15, acolb = (lane >> 4) * 16;
    const int brow = (lane & 7) | ((lane & 16) >> 1), bcolb = (lane & 8) * 2;
    const int erow = lane >> 2, ecol = (lane & 3) * 2;

    int buf = 0;   // also selects s_xq half
    // prologue: stage + convert first tile into buf 0, xsq -> s_xq[0]
    if (blockIdx.x < NT) {
#pragma unroll
        for (int h = 0; h < 2; h++) {
            stageX(blockIdx.x, h);
            CP_WAIT(0);
            __syncthreads();
            convX(h, 0);
            __syncthreads();
        }
        if (tid < 64) {
            float s = 0.f;
#pragma unroll
            for (int j = 0; j < 16; j++) s += partq[tid * 16 + j];
            s_xq[tid] = s;
        }
        __syncthreads();
    }

    for (int tile = blockIdx.x; tile < NT; tile += 148) {
        const int bm = tile * 64;
        const bool nxt = (tile + 148 < NT);
        if (tid < 8) s_fl[tid] = 0;
        __syncthreads();

        if (nxt) stageX(tile + 148, 0);

        float acc[2][8][4] = {};
        const uint32_t abase = sbase + (uint32_t)(SM_A + buf * 64 * PB);

        // ---- MMA first half: kk 0..3 ----
#pragma unroll
        for (int kk = 0; kk < 4; kk++) {
            uint32_t af[2][4], bfr[4][4];
#pragma unroll
            for (int mf = 0; mf < 2; mf++)
                ldsm4(af[mf], abase + (uint32_t)((wr * 32 + mf * 16 + arow) * PB +
                                                 kk * 32 + acolb));
#pragma unroll
            for (int nh = 0; nh < 4; nh++)
                ldsm4(bfr[nh], sbase + (uint32_t)((wc * 64 + nh * 16 + brow) * PB +
                                                  kk * 32 + bcolb));
#pragma unroll
            for (int mf = 0; mf < 2; mf++)
#pragma unroll
                for (int nf = 0; nf < 8; nf++)
                    mma_fp8(acc[mf][nf], af[mf],
                            bfr[nf >> 1][(nf & 1) * 2], bfr[nf >> 1][(nf & 1) * 2 + 1]);
        }

        if (nxt) {   // convert chunk0 of next tile, launch chunk1
            CP_WAIT(0);
            __syncthreads();
            convX(0, buf ^ 1);
            __syncthreads();
            stageX(tile + 148, 1);
        }

        // ---- MMA second half: kk 4..7 ----
#pragma unroll
        for (int kk = 4; kk < 8; kk++) {
            uint32_t af[2][4], bfr[4][4];
#pragma unroll
            for (int mf = 0; mf < 2; mf++)
                ldsm4(af[mf], abase + (uint32_t)((wr * 32 + mf * 16 + arow) * PB +
                                                 kk * 32 + acolb));
#pragma unroll
            for (int nh = 0; nh < 4; nh++)
                ldsm4(bfr[nh], sbase + (uint32_t)((wc * 64 + nh * 16 + brow) * PB +
                                                  kk * 32 + bcolb));
#pragma unroll
            for (int mf = 0; mf < 2; mf++)
#pragma unroll
                for (int nf = 0; nf < 8; nf++)
                    mma_fp8(acc[mf][nf], af[mf],
                            bfr[nf >> 1][(nf & 1) * 2], bfr[nf >> 1][(nf & 1) * 2 + 1]);
        }

        if (nxt) {   // convert chunk1, finalize next tile's xsq
            CP_WAIT(0);
            __syncthreads();
            convX(1, buf ^ 1);
            __syncthreads();
            if (tid < 64) {
                float s = 0.f;
#pragma unroll
                for (int j = 0; j < 16; j++) s += partq[tid * 16 + j];
                s_xq[(buf ^ 1) * 64 + tid] = s;
            }
        }

        // ---------- RBF epilogue with threshold gate ----------
        const float* xq = s_xq + buf * 64;
        float tmax = -1e30f;
#pragma unroll
        for (int mf = 0; mf < 2; mf++) {
            const int lr0 = wr * 32 + mf * 16 + erow;
            const float xq0 = xq[lr0], xq1 = xq[lr0 + 8];
#pragma unroll
            for (int nf = 0; nf < 8; nf++) {
                const int gc = wc * 64 + nf * 8 + ecol;
                const float cq0 = s_cq[gc], ss0 = s_cs[gc];
                const float cq1 = s_cq[gc + 1], ss1 = s_cs[gc + 1];
                acc[mf][nf][0] = (2.f * acc[mf][nf][0] - xq0 - cq0) * ss0;
                acc[mf][nf][1] = (2.f * acc[mf][nf][1] - xq0 - cq1) * ss1;
                acc[mf][nf][2] = (2.f * acc[mf][nf][2] - xq1 - cq0) * ss0;
                acc[mf][nf][3] = (2.f * acc[mf][nf][3] - xq1 - cq1) * ss1;
                tmax = fmaxf(tmax, fmaxf(fmaxf(acc[mf][nf][0], acc[mf][nf][1]),
                                         fmaxf(acc[mf][nf][2], acc[mf][nf][3])));
            }
        }
#pragma unroll
        for (int o = 16; o > 0; o >>= 1)
            tmax = fmaxf(tmax, __shfl_xor_sync(0xffffffffu, tmax, o));

        if (tmax >= -93.0f) {   // exp rounds to bf16 zero iff arg < -92.87
            uint32_t nzu = 0;
#pragma unroll
            for (int mf = 0; mf < 2; mf++) {
                const int gm0 = bm + wr * 32 + mf * 16 + erow;
#pragma unroll
                for (int nf = 0; nf < 8; nf++) {
                    const int gc = wc * 64 + nf * 8 + ecol;
                    float v00 = __expf(acc[mf][nf][0]);
                    float v01 = __expf(acc[mf][nf][1]);
                    float v10 = __expf(acc[mf][nf][2]);
                    float v11 = __expf(acc[mf][nf][3]);
                    __nv_bfloat162 h0 = __floats2bfloat162_rn(v00, v01);
                    __nv_bfloat162 h1 = __floats2bfloat162_rn(v10, v11);
                    const uint32_t p0 = *(uint32_t*)&h0, p1 = *(uint32_t*)&h1;
                    nzu |= p0 | p1;
                    if (p0) *(uint32_t*)(g_scaled + (size_t)gm0 * G_DIM + gc) = p0;
                    if (p1) *(uint32_t*)(g_scaled + (size_t)(gm0 + 8) * G_DIM + gc) = p1;
                }
            }
            nzu = __reduce_or_sync(0xffffffffu, nzu);
            if (lane == 0 && nzu) atomicOr(&s_fl[wc], 1);
        }
        __syncthreads();

        int nz = 0;
#pragma unroll
        for (int k = 0; k < 8; k++) nz |= s_fl[k];

        if (nz == 0) {
            // fast path: broadcast ybuf to 64 rows
            const float4* y4 = (const float4*)ybuf;
            float4* o4 = (float4*)(out + (size_t)bm * W_DIM);
#pragma unroll
            for (int i = 0; i < 16; i++) {
                const int idx = tid + i * 512;
                __stcs(o4 + idx, y4[idx & 127]);
            }
        } else {
            // slow path: exact SIMT GEMM2 + LN (rarely taken)
            int fl[8];
#pragma unroll
            for (int k = 0; k < 8; k++) fl[k] = s_fl[k];
            for (int r = 0; r < 64; r++) {
                float a = vs_b[tid];
                for (int i = 0; i < 8; i++) {
                    if (!fl[i]) continue;
                    for (int j = 0; j < 64; j++) {
                        const int g = i * 64 + j;
                        a += __bfloat162float(g_scaled[(size_t)(bm + r) * G_DIM + g]) *
                             __bfloat162float(g_wb[(size_t)tid * G_DIM + g]);
                    }
                }
                float s = a, q = a * a;
#pragma unroll
                for (int o = 16; o > 0; o >>= 1) {
                    s += __shfl_xor_sync(0xffffffffu, s, o);
                    q += __shfl_xor_sync(0xffffffffu, q, o);
                }
                if (lane == 0) { red[wid] = s; red[wid + 16] = q; }
                __syncthreads();
                if (tid == 0) {
                    float ts = 0.f, tq = 0.f;
#pragma unroll
                    for (int w = 0; w < 16; w++) { ts += red[w]; tq += red[w + 16]; }
                    const float mean = ts * (1.0f / 512.0f);
                    const float var  = tq * (1.0f / 512.0f) - mean * mean;
                    red[0] = mean; red[1] = rsqrtf(var + LN_EPS);
                }
                __syncthreads();
                out[(size_t)(bm + r) * W_DIM + tid] =
                    tanhf((a - red[0]) * red[1] * vs_g[tid] + vs_be[tid]);
                __syncthreads();
            }
        }
        buf ^= 1;
        __syncthreads();
    }
}

// ---------------------------------------------------------------------------
extern "C" void kernel_launch(void* const* d_in, const int* in_sizes, int n_in,
                              void* d_out, int out_size) {
    const float* inputs     = (const float*)d_in[0];
    const float* centers    = (const float*)d_in[1];
    const float* log_scales = (const float*)d_in[2];
    const float* W_mix      = (const float*)d_in[3];
    const float* b_mix      = (const float*)d_in[4];
    const float* ln_gamma   = (const float*)d_in[5];
    const float* ln_beta    = (const float*)d_in[6];
    float* out = (float*)d_out;

    cudaFuncSetAttribute(fused_kan, cudaFuncAttributeMaxDynamicSharedMemorySize, F_SMEM);

    conv_cw<<<128, 256>>>(centers, log_scales, W_mix);
    fused_kan<<<148, 512, F_SMEM>>>(inputs, b_mix, ln_gamma, ln_beta, out);
}

// round 17
// speedup vs baseline: 2.6132x; 1.2695x over previous
#include <cuda_runtime.h>
#include <cuda_bf16.h>
#include <cuda_fp8.h>
#include <math.h>
#include <stdint.h>

#define B_ROWS 65536
#define IN_DIM 256
#define G_DIM  512
#define W_DIM  512
#define LN_EPS 1e-5f

// ---------------- global scratch (device globals; no allocs) ----------------
__device__ uint8_t g_c8[(size_t)G_DIM * IN_DIM];           // centers e4m3
__device__ __nv_bfloat16 g_wb[(size_t)W_DIM * G_DIM];      // W_mix bf16
__device__ __nv_bfloat16 g_scaled[(size_t)B_ROWS * G_DIM]; // RBF activations bf16
__device__ float g_csq[G_DIM];
__device__ float g_csqh[G_DIM];                            // first-128-dim partial
__device__ float g_s[G_DIM];

// ---------------- PTX helpers (sm_80/89+ subset; compute_103-safe) ----------
__device__ __forceinline__ uint32_t smem_cast(const void* p) {
    return (uint32_t)__cvta_generic_to_shared(p);
}
__device__ __forceinline__ void cp16(uint32_t dst, const void* src) {
    asm volatile("cp.async.cg.shared.global [%0], [%1], 16;" :: "r"(dst), "l"(src));
}
#define CP_COMMIT() asm volatile("cp.async.commit_group;" ::: "memory")
#define CP_WAIT(n)  asm volatile("cp.async.wait_group %0;" :: "n"(n) : "memory")

__device__ __forceinline__ void ldsm4(uint32_t* r, uint32_t addr) {
    asm volatile("ldmatrix.sync.aligned.m8n8.x4.shared.b16 {%0,%1,%2,%3}, [%4];"
                 : "=r"(r[0]), "=r"(r[1]), "=r"(r[2]), "=r"(r[3]) : "r"(addr));
}
__device__ __forceinline__ void mma_fp8(float* d, const uint32_t* a,
                                        uint32_t b0, uint32_t b1) {
    asm volatile(
        "mma.sync.aligned.m16n8k32.row.col.f32.e4m3.e4m3.f32 "
        "{%0,%1,%2,%3}, {%4,%5,%6,%7}, {%8,%9}, {%0,%1,%2,%3};"
        : "+f"(d[0]), "+f"(d[1]), "+f"(d[2]), "+f"(d[3])
        : "r"(a[0]), "r"(a[1]), "r"(a[2]), "r"(a[3]), "r"(b0), "r"(b1));
}

__device__ __forceinline__ ushort4 cvt8_e4m3(float4 a0, float4 a1) {
    ushort4 u;
    u.x = __nv_cvt_float2_to_fp8x2(make_float2(a0.x, a0.y), __NV_SATFINITE, __NV_E4M3);
    u.y = __nv_cvt_float2_to_fp8x2(make_float2(a0.z, a0.w), __NV_SATFINITE, __NV_E4M3);
    u.z = __nv_cvt_float2_to_fp8x2(make_float2(a1.x, a1.y), __NV_SATFINITE, __NV_E4M3);
    u.w = __nv_cvt_float2_to_fp8x2(make_float2(a1.z, a1.w), __NV_SATFINITE, __NV_E4M3);
    return u;
}

// ---------------- prep kernel: centers + W only ------------------------------
__global__ __launch_bounds__(256) void conv_cw(const float* __restrict__ c,
                                               const float* __restrict__ ls,
                                               const float* __restrict__ w) {
    const int lane = threadIdx.x & 31;
    if (blockIdx.x < 64) {
        int g = blockIdx.x * 8 + (threadIdx.x >> 5);
        const float* r = c + (size_t)g * IN_DIM;
        int k0 = lane * 8;
        float4 a0 = *(const float4*)(r + k0);
        float4 a1 = *(const float4*)(r + k0 + 4);
        float ss = a0.x*a0.x + a0.y*a0.y + a0.z*a0.z + a0.w*a0.w +
                   a1.x*a1.x + a1.y*a1.y + a1.z*a1.z + a1.w*a1.w;
        float sh = (lane < 16) ? ss : 0.f;   // dims [0,128)
#pragma unroll
        for (int o = 16; o > 0; o >>= 1) {
            ss += __shfl_xor_sync(0xffffffffu, ss, o);
            sh += __shfl_xor_sync(0xffffffffu, sh, o);
        }
        if (lane == 0) { g_csq[g] = ss; g_csqh[g] = sh; g_s[g] = expf(ls[g]); }
        *(ushort4*)(g_c8 + (size_t)g * IN_DIM + k0) = cvt8_e4m3(a0, a1);
    } else {
        int wr = (blockIdx.x - 64) * 8 + (threadIdx.x >> 5);
        const float* r = w + (size_t)wr * G_DIM;
#pragma unroll
        for (int part = 0; part < 2; part++) {
            int k0 = lane * 16 + part * 8;
            float4 a0 = *(const float4*)(r + k0);
            float4 a1 = *(const float4*)(r + k0 + 4);
            __nv_bfloat162 h0 = __floats2bfloat162_rn(a0.x, a0.y);
            __nv_bfloat162 h1 = __floats2bfloat162_rn(a0.z, a0.w);
            __nv_bfloat162 h2 = __floats2bfloat162_rn(a1.x, a1.y);
            __nv_bfloat162 h3 = __floats2bfloat162_rn(a1.z, a1.w);
            *(uint4*)(g_wb + (size_t)wr * G_DIM + k0) =
                make_uint4(*(uint32_t*)&h0, *(uint32_t*)&h1, *(uint32_t*)&h2, *(uint32_t*)&h3);
        }
    }
}

// ---------------- fused conv + RBF-GEMM + GEMM2 + LN + tanh ------------------
// Persistent: 148 CTAs x 512 threads. Centers fp8 resident in SMEM.
// Per tile: fp32 A staged + converted to fp8 (+ xsq partials) overlapped with
// MMA; HALFWAY GATE: after K=128 of 256, dist2_128 lower-bounds dist2_full,
// so if max arg_half < -103 the whole tile is bf16-zero -> skip MMA 4..7 and
// the epilogue. Otherwise full path with the -93 per-warp gate.
#define PB 272
#define SM_A (512 * PB)                       // two 64-row fp8 A buffers
#define SM_X (SM_A + 2 * 64 * PB)             // fp32 staging (32 rows, pitch 1040)
#define SM_F (SM_X + 32 * 1040)               // float section (bytes)
#define F_SMEM (SM_F + (512 * 7 + 32 + 128 + 128 + 1024 + 16 + 8) * 4)
#define NT (B_ROWS / 64)

__global__ __launch_bounds__(512, 1) void fused_kan(const float* __restrict__ xin,
                                                    const float* __restrict__ bias,
                                                    const float* __restrict__ gamma,
                                                    const float* __restrict__ beta,
                                                    float* __restrict__ out) {
    extern __shared__ __align__(16) uint8_t sm[];
    float* s_cq  = (float*)(sm + SM_F);
    float* s_cqh = s_cq + 512;
    float* s_cs  = s_cqh + 512;
    float* vs_b  = s_cs + 512;
    float* vs_g  = vs_b + 512;
    float* vs_be = vs_g + 512;
    float* ybuf  = vs_be + 512;
    float* red   = ybuf + 512;        // 32
    float* s_xq  = red + 32;          // 2 x 64 (full row sums)
    float* s_xqh = s_xq + 128;        // 2 x 64 (first-128 partials)
    float* partq = s_xqh + 128;       // 64 x 16 xsq partials
    float* s_gm  = partq + 1024;      // 16 warp maxima
    int*   s_fl  = (int*)(s_gm + 16);

    const int tid = threadIdx.x, lane = tid & 31, wid = tid >> 5;
    const uint32_t sbase = smem_cast(sm);

    s_cq[tid] = g_csq[tid]; s_cqh[tid] = g_csqh[tid]; s_cs[tid] = g_s[tid];
    vs_b[tid] = bias[tid];  vs_g[tid] = gamma[tid]; vs_be[tid] = beta[tid];

    // centers (512 x 256B fp8) resident: 16 cp16/thread
#pragma unroll
    for (int i = 0; i < 16; i++) {
        const int v = tid + i * 512;
        const int row = v >> 4, cb = (v & 15) * 16;
        cp16(sbase + (uint32_t)(row * PB + cb), g_c8 + (size_t)row * IN_DIM + cb);
    }
    CP_COMMIT();
    __syncthreads();

    // once per CTA: ybuf = tanh(LN(bias))
    {
        const float v = vs_b[tid];
        float s = v, q = v * v;
#pragma unroll
        for (int o = 16; o > 0; o >>= 1) {
            s += __shfl_xor_sync(0xffffffffu, s, o);
            q += __shfl_xor_sync(0xffffffffu, q, o);
        }
        if (lane == 0) { red[wid] = s; red[wid + 16] = q; }
        __syncthreads();
        if (tid == 0) {
            float ts = 0.f, tq = 0.f;
#pragma unroll
            for (int w = 0; w < 16; w++) { ts += red[w]; tq += red[w + 16]; }
            const float mean = ts * (1.0f / 512.0f);
            const float var  = tq * (1.0f / 512.0f) - mean * mean;
            red[0] = mean; red[1] = rsqrtf(var + LN_EPS);
        }
        __syncthreads();
        ybuf[tid] = tanhf((v - red[0]) * red[1] * vs_g[tid] + vs_be[tid]);
    }
    __syncthreads();

    auto stageX = [&](int t, int h) {
#pragma unroll
        for (int i = 0; i < 4; i++) {
            const int idx = tid + i * 512;
            const int row = idx >> 6, c16 = idx & 63;
            cp16(sbase + (uint32_t)(SM_X + row * 1040 + c16 * 16),
                 xin + ((size_t)(t * 64 + h * 32 + row) * IN_DIM + c16 * 4));
        }
        CP_COMMIT();
    };
    auto convX = [&](int h, int db) {
        const int row = tid & 31, seg = tid >> 5;
        float4 f0 = *(const float4*)(sm + SM_X + row * 1040 + seg * 64);
        float4 f1 = *(const float4*)(sm + SM_X + row * 1040 + seg * 64 + 16);
        float4 f2 = *(const float4*)(sm + SM_X + row * 1040 + seg * 64 + 32);
        float4 f3 = *(const float4*)(sm + SM_X + row * 1040 + seg * 64 + 48);
        ushort4 ua = cvt8_e4m3(f0, f1);
        ushort4 ub = cvt8_e4m3(f2, f3);
        uint4 wv;
        wv.x = (uint32_t)ua.x | ((uint32_t)ua.y << 16);
        wv.y = (uint32_t)ua.z | ((uint32_t)ua.w << 16);
        wv.z = (uint32_t)ub.x | ((uint32_t)ub.y << 16);
        wv.w = (uint32_t)ub.z | ((uint32_t)ub.w << 16);
        *(uint4*)(sm + SM_A + db * 64 * PB + (h * 32 + row) * PB + seg * 16) = wv;
        float ss = f0.x*f0.x + f0.y*f0.y + f0.z*f0.z + f0.w*f0.w +
                   f1.x*f1.x + f1.y*f1.y + f1.z*f1.z + f1.w*f1.w +
                   f2.x*f2.x + f2.y*f2.y + f2.z*f2.z + f2.w*f2.w +
                   f3.x*f3.x + f3.y*f3.y + f3.z*f3.z + f3.w*f3.w;
        partq[(h * 32 + row) * 16 + seg] = ss;
    };
    auto finQ = [&](int db) {   // per-row xsq: half (segs 0..7) + full
        if (tid < 64) {
            float sh = 0.f, sf = 0.f;
#pragma unroll
            for (int j = 0; j < 8; j++) sh += partq[tid * 16 + j];
#pragma unroll
            for (int j = 8; j < 16; j++) sf += partq[tid * 16 + j];
            s_xqh[db * 64 + tid] = sh;
            s_xq[db * 64 + tid] = sh + sf;
        }
    };

    const int wr = wid >> 3, wc = wid & 7;
    const int arow = lane & 15, acolb = (lane >> 4) * 16;
    const int brow = (lane & 7) | ((lane & 16) >> 1), bcolb = (lane & 8) * 2;
    const int erow = lane >> 2, ecol = (lane & 3) * 2;

    int buf = 0;
    if (blockIdx.x < NT) {
#pragma unroll
        for (int h = 0; h < 2; h++) {
            stageX(blockIdx.x, h);
            CP_WAIT(0);
            __syncthreads();
            convX(h, 0);
            __syncthreads();
        }
        finQ(0);
        __syncthreads();
    }

    for (int tile = blockIdx.x; tile < NT; tile += 148) {
        const int bm = tile * 64;
        const bool nxt = (tile + 148 < NT);
        if (tid < 8) s_fl[tid] = 0;
        __syncthreads();

        if (nxt) stageX(tile + 148, 0);

        float acc[2][8][4] = {};
        const uint32_t abase = sbase + (uint32_t)(SM_A + buf * 64 * PB);

        // ---- MMA first half: kk 0..3 (dims [0,128)) ----
#pragma unroll
        for (int kk = 0; kk < 4; kk++) {
            uint32_t af[2][4], bfr[4][4];
#pragma unroll
            for (int mf = 0; mf < 2; mf++)
                ldsm4(af[mf], abase + (uint32_t)((wr * 32 + mf * 16 + arow) * PB +
                                                 kk * 32 + acolb));
#pragma unroll
            for (int nh = 0; nh < 4; nh++)
                ldsm4(bfr[nh], sbase + (uint32_t)((wc * 64 + nh * 16 + brow) * PB +
                                                  kk * 32 + bcolb));
#pragma unroll
            for (int mf = 0; mf < 2; mf++)
#pragma unroll
                for (int nf = 0; nf < 8; nf++)
                    mma_fp8(acc[mf][nf], af[mf],
                            bfr[nf >> 1][(nf & 1) * 2], bfr[nf >> 1][(nf & 1) * 2 + 1]);
        }

        if (nxt) {
            CP_WAIT(0);
            __syncthreads();
            convX(0, buf ^ 1);
            __syncthreads();
            stageX(tile + 148, 1);
        }

        // ---- HALFWAY GATE: arg_half upper-bounds final exp argument ----
        {
            const float* xqh = s_xqh + buf * 64;
            float gmax = -1e30f;
#pragma unroll
            for (int mf = 0; mf < 2; mf++) {
                const int lr0 = wr * 32 + mf * 16 + erow;
                const float xh0 = xqh[lr0], xh1 = xqh[lr0 + 8];
#pragma unroll
                for (int nf = 0; nf < 8; nf++) {
                    const int gc = wc * 64 + nf * 8 + ecol;
                    const float ch0 = s_cqh[gc], sl0 = s_cs[gc];
                    const float ch1 = s_cqh[gc + 1], sl1 = s_cs[gc + 1];
                    gmax = fmaxf(gmax, (2.f * acc[mf][nf][0] - xh0 - ch0) * sl0);
                    gmax = fmaxf(gmax, (2.f * acc[mf][nf][1] - xh0 - ch1) * sl1);
                    gmax = fmaxf(gmax, (2.f * acc[mf][nf][2] - xh1 - ch0) * sl0);
                    gmax = fmaxf(gmax, (2.f * acc[mf][nf][3] - xh1 - ch1) * sl1);
                }
            }
#pragma unroll
            for (int o = 16; o > 0; o >>= 1)
                gmax = fmaxf(gmax, __shfl_xor_sync(0xffffffffu, gmax, o));
            if (lane == 0) s_gm[wid] = gmax;
        }
        __syncthreads();
        float tm = -1e30f;
#pragma unroll
        for (int w = 0; w < 16; w++) tm = fmaxf(tm, s_gm[w]);
        const bool skip = (tm < -103.0f);   // 10-margin below the -92.87 cutoff

        if (!skip) {
            // ---- MMA second half: kk 4..7 ----
#pragma unroll
            for (int kk = 4; kk < 8; kk++) {
                uint32_t af[2][4], bfr[4][4];
#pragma unroll
                for (int mf = 0; mf < 2; mf++)
                    ldsm4(af[mf], abase + (uint32_t)((wr * 32 + mf * 16 + arow) * PB +
                                                     kk * 32 + acolb));
#pragma unroll
                for (int nh = 0; nh < 4; nh++)
                    ldsm4(bfr[nh], sbase + (uint32_t)((wc * 64 + nh * 16 + brow) * PB +
                                                      kk * 32 + bcolb));
#pragma unroll
                for (int mf = 0; mf < 2; mf++)
#pragma unroll
                    for (int nf = 0; nf < 8; nf++)
                        mma_fp8(acc[mf][nf], af[mf],
                                bfr[nf >> 1][(nf & 1) * 2], bfr[nf >> 1][(nf & 1) * 2 + 1]);
            }
        }

        if (nxt) {
            CP_WAIT(0);
            __syncthreads();
            convX(1, buf ^ 1);
            __syncthreads();
            finQ(buf ^ 1);
        }

        if (!skip) {
            // ---- full RBF epilogue with -93 per-warp gate ----
            const float* xq = s_xq + buf * 64;
            float tmax = -1e30f;
#pragma unroll
            for (int mf = 0; mf < 2; mf++) {
                const int lr0 = wr * 32 + mf * 16 + erow;
                const float xq0 = xq[lr0], xq1 = xq[lr0 + 8];
#pragma unroll
                for (int nf = 0; nf < 8; nf++) {
                    const int gc = wc * 64 + nf * 8 + ecol;
                    const float cq0 = s_cq[gc], ss0 = s_cs[gc];
                    const float cq1 = s_cq[gc + 1], ss1 = s_cs[gc + 1];
                    acc[mf][nf][0] = (2.f * acc[mf][nf][0] - xq0 - cq0) * ss0;
                    acc[mf][nf][1] = (2.f * acc[mf][nf][1] - xq0 - cq1) * ss1;
                    acc[mf][nf][2] = (2.f * acc[mf][nf][2] - xq1 - cq0) * ss0;
                    acc[mf][nf][3] = (2.f * acc[mf][nf][3] - xq1 - cq1) * ss1;
                    tmax = fmaxf(tmax, fmaxf(fmaxf(acc[mf][nf][0], acc[mf][nf][1]),
                                             fmaxf(acc[mf][nf][2], acc[mf][nf][3])));
                }
            }
#pragma unroll
            for (int o = 16; o > 0; o >>= 1)
                tmax = fmaxf(tmax, __shfl_xor_sync(0xffffffffu, tmax, o));

            if (tmax >= -93.0f) {
                uint32_t nzu = 0;
#pragma unroll
                for (int mf = 0; mf < 2; mf++) {
                    const int gm0 = bm + wr * 32 + mf * 16 + erow;
#pragma unroll
                    for (int nf = 0; nf < 8; nf++) {
                        const int gc = wc * 64 + nf * 8 + ecol;
                        float v00 = __expf(acc[mf][nf][0]);
                        float v01 = __expf(acc[mf][nf][1]);
                        float v10 = __expf(acc[mf][nf][2]);
                        float v11 = __expf(acc[mf][nf][3]);
                        __nv_bfloat162 h0 = __floats2bfloat162_rn(v00, v01);
                        __nv_bfloat162 h1 = __floats2bfloat162_rn(v10, v11);
                        const uint32_t p0 = *(uint32_t*)&h0, p1 = *(uint32_t*)&h1;
                        nzu |= p0 | p1;
                        if (p0) *(uint32_t*)(g_scaled + (size_t)gm0 * G_DIM + gc) = p0;
                        if (p1) *(uint32_t*)(g_scaled + (size_t)(gm0 + 8) * G_DIM + gc) = p1;
                    }
                }
                nzu = __reduce_or_sync(0xffffffffu, nzu);
                if (lane == 0 && nzu) atomicOr(&s_fl[wc], 1);
            }
        }
        __syncthreads();

        int nz = 0;
#pragma unroll
        for (int k = 0; k < 8; k++) nz |= s_fl[k];

        if (nz == 0) {
            // fast path: broadcast ybuf to 64 rows
            const float4* y4 = (const float4*)ybuf;
            float4* o4 = (float4*)(out + (size_t)bm * W_DIM);
#pragma unroll
            for (int i = 0; i < 16; i++) {
                const int idx = tid + i * 512;
                __stcs(o4 + idx, y4[idx & 127]);
            }
        } else {
            // slow path: exact SIMT GEMM2 + LN (rarely taken)
            int fl[8];
#pragma unroll
            for (int k = 0; k < 8; k++) fl[k] = s_fl[k];
            for (int r = 0; r < 64; r++) {
                float a = vs_b[tid];
                for (int i = 0; i < 8; i++) {
                    if (!fl[i]) continue;
                    for (int j = 0; j < 64; j++) {
                        const int g = i * 64 + j;
                        a += __bfloat162float(g_scaled[(size_t)(bm + r) * G_DIM + g]) *
                             __bfloat162float(g_wb[(size_t)tid * G_DIM + g]);
                    }
                }
                float s = a, q = a * a;
#pragma unroll
                for (int o = 16; o > 0; o >>= 1) {
                    s += __shfl_xor_sync(0xffffffffu, s, o);
                    q += __shfl_xor_sync(0xffffffffu, q, o);
                }
                if (lane == 0) { red[wid] = s; red[wid + 16] = q; }
                __syncthreads();
                if (tid == 0) {
                    float ts = 0.f, tq = 0.f;
#pragma unroll
                    for (int w = 0; w < 16; w++) { ts += red[w]; tq += red[w + 16]; }
                    const float mean = ts * (1.0f / 512.0f);
                    const float var  = tq * (1.0f / 512.0f) - mean * mean;
                    red[0] = mean; red[1] = rsqrtf(var + LN_EPS);
                }
                __syncthreads();
                out[(size_t)(bm + r) * W_DIM + tid] =
                    tanhf((a - red[0]) * red[1] * vs_g[tid] + vs_be[tid]);
                __syncthreads();
            }
        }
        buf ^= 1;
        __syncthreads();
    }
}

// ---------------------------------------------------------------------------
extern "C" void kernel_launch(void* const* d_in, const int* in_sizes, int n_in,
                              void* d_out, int out_size) {
    const float* inputs     = (const float*)d_in[0];
    const float* centers    = (const float*)d_in[1];
    const float* log_scales = (const float*)d_in[2];
    const float* W_mix      = (const float*)d_in[3];
    const float* b_mix      = (const float*)d_in[4];
    const float* ln_gamma   = (const float*)d_in[5];
    const float* ln_beta    = (const float*)d_in[6];
    float* out = (float*)d_out;

    cudaFuncSetAttribute(fused_kan, cudaFuncAttributeMaxDynamicSharedMemorySize, F_SMEM);

    conv_cw<<<128, 256>>>(centers, log_scales, W_mix);
    fused_kan<<<148, 512, F_SMEM>>>(inputs, b_mix, ln_gamma, ln_beta, out);
}